// round 4
// baseline (speedup 1.0000x reference)
#include <cuda_runtime.h>
#include <math.h>

// Problem shapes (fixed)
#define B_SZ 1024
#define N_SZ 100000
#define D_SZ 512
#define D4   128               // float4 per row
#define BM   32                // rows per CTA (8 warps x 4 rows)
#define BN   64                // keys per tile (2 keys per lane)
#define NSPLIT 9
#define SPL  11112             // ceil(N/NSPLIT)
#define THREADS 256
#define NROWBLK (B_SZ/BM)      // 32

#define SMEM_BYTES (BM*D4*16 + D4*BN*16 + BM*BN*8)   // 65536+131072+16384 = 212992

// Scratch
__device__ float g_ml[B_SZ * NSPLIT * 2];
__device__ float g_acc[(size_t)B_SZ * NSPLIT * D_SZ];
__device__ int   g_cnt[NROWBLK];   // zero-initialized; last CTA resets after use

// ---- packed f32x2 helpers (SASS FFMA2 — only reachable via PTX) ----
typedef unsigned long long u64;
__device__ __forceinline__ u64 pack2(float a, float b) {
    u64 r; asm("mov.b64 %0,{%1,%2};" : "=l"(r) : "f"(a), "f"(b)); return r;
}
__device__ __forceinline__ void unpack2(u64 v, float& a, float& b) {
    asm("mov.b64 {%0,%1},%2;" : "=f"(a), "=f"(b) : "l"(v));
}
__device__ __forceinline__ void ffma2(u64& d, u64 a, u64 b) {
    asm("fma.rn.f32x2 %0,%1,%2,%0;" : "+l"(d) : "l"(a), "l"(b));
}
__device__ __forceinline__ void fmul2(u64& d, u64 a) {
    asm("mul.rn.f32x2 %0,%0,%1;" : "+l"(d) : "l"(a));
}

// ---------------------------------------------------------------------------
// One fused kernel: flash pass (QK + online softmax + PV) with on-the-fly
// dataset norms, split-K over keys, and last-CTA-per-row-block combine epilogue.
// logit'[b][n] = (a/b^2) * <x_b,y_n> - (a^2/(2b^2)) * ||y_n||^2   (||x||^2 cancels)
// v = (-1/b) x + (1 + a/b) * softmax-weighted dataset
// ---------------------------------------------------------------------------
__global__ __launch_bounds__(THREADS, 1) void flash_kernel(
    const float* __restrict__ x, const float* __restrict__ t,
    const float* __restrict__ y, float* __restrict__ out)
{
    extern __shared__ char smem_raw[];
    ulonglong2* sx = (ulonglong2*)smem_raw;          // BM*D4 (float4 each)
    ulonglong2* sy = sx + BM * D4;                   // D4*BN, swizzled
    u64*        sp = (u64*)(sy + (size_t)D4 * BN);   // BM*BN packed {p,p}
    __shared__ int s_last;

    const int tid  = threadIdx.x;
    const int lane = tid & 31;
    const int warp = tid >> 5;
    const int rb      = blockIdx.x;
    const int r0      = rb * BM;
    const int split   = blockIdx.y;
    const int n_begin = split * SPL;
    const int n_end   = min(n_begin + SPL, N_SZ);

    // query tile -> smem
    const float4* x4 = (const float4*)x;
    for (int i = tid; i < BM * D4; i += THREADS)
        ((float4*)sx)[i] = x4[(size_t)r0 * D4 + i];

    // per-row coefficients (4 rows per warp)
    float al[4], be[4];
    #pragma unroll
    for (int r = 0; r < 4; r++) {
        float tv = t[r0 + warp * 4 + r];
        float a = tv, b = 1.f - tv;
        al[r] = a / (b * b);
        be[r] = a * a / (2.f * b * b);
    }

    float mrun[4] = {-INFINITY, -INFINITY, -INFINITY, -INFINITY};
    float lrun[4] = {0.f, 0.f, 0.f, 0.f};
    u64 acc[4][8];                       // lane owns d4 = lane+32k -> 2 u64 per k
    #pragma unroll
    for (int r = 0; r < 4; r++)
        #pragma unroll
        for (int i = 0; i < 8; i++) acc[r][i] = 0ull;

    const float4* y4g = (const float4*)y;
    const int nl0 = lane, nl1 = lane + 32;

    for (int n0 = n_begin; n0 < n_end; n0 += BN) {
        __syncthreads();
        // key tile -> smem (swizzled: float4 (n,j) at sy[j*BN + (n ^ (j&63))])
        for (int i = tid; i < BN * D4; i += THREADS) {
            int n = i >> 7, j = i & 127;
            float4 v = make_float4(0.f, 0.f, 0.f, 0.f);
            if (n0 + n < n_end) v = y4g[(size_t)(n0 + n) * D4 + j];
            ((float4*)sy)[j * BN + (n ^ (j & 63))] = v;
        }
        __syncthreads();

        // ---- QK (+ on-the-fly key norms) ----
        u64 s[4][2];
        #pragma unroll
        for (int r = 0; r < 4; r++) { s[r][0] = 0ull; s[r][1] = 0ull; }
        u64 ny0 = 0ull, ny1 = 0ull;

        #pragma unroll 4
        for (int j = 0; j < D4; j++) {
            int c = j & 63;
            ulonglong2 yv0 = sy[j * BN + (nl0 ^ c)];
            ulonglong2 yv1 = sy[j * BN + (nl1 ^ c)];
            ffma2(ny0, yv0.x, yv0.x); ffma2(ny0, yv0.y, yv0.y);
            ffma2(ny1, yv1.x, yv1.x); ffma2(ny1, yv1.y, yv1.y);
            #pragma unroll
            for (int r = 0; r < 4; r++) {
                ulonglong2 xv = sx[(warp * 4 + r) * D4 + j];   // broadcast
                ffma2(s[r][0], xv.x, yv0.x); ffma2(s[r][0], xv.y, yv0.y);
                ffma2(s[r][1], xv.x, yv1.x); ffma2(s[r][1], xv.y, yv1.y);
            }
        }

        bool v0 = (n0 + nl0) < n_end;
        bool v1 = (n0 + nl1) < n_end;
        float t0, t1;
        unpack2(ny0, t0, t1); float dn0 = t0 + t1;
        unpack2(ny1, t0, t1); float dn1 = t0 + t1;

        float lg0[4], lg1[4];
        #pragma unroll
        for (int r = 0; r < 4; r++) {
            float slo, shi, sv;
            unpack2(s[r][0], slo, shi); sv = slo + shi;
            lg0[r] = v0 ? fmaf(al[r], sv, -be[r] * dn0) : -INFINITY;
            unpack2(s[r][1], slo, shi); sv = slo + shi;
            lg1[r] = v1 ? fmaf(al[r], sv, -be[r] * dn1) : -INFINITY;
        }

        // ---- online softmax (4 rows) ----
        #pragma unroll
        for (int r = 0; r < 4; r++) {
            float mt = fmaxf(lg0[r], lg1[r]);
            #pragma unroll
            for (int off = 16; off > 0; off >>= 1)
                mt = fmaxf(mt, __shfl_xor_sync(0xffffffffu, mt, off));
            float mnew = fmaxf(mrun[r], mt);
            float sc = (mrun[r] == -INFINITY) ? 0.f : __expf(mrun[r] - mnew);
            float p0 = __expf(lg0[r] - mnew);
            float p1 = __expf(lg1[r] - mnew);
            float ps = p0 + p1;
            #pragma unroll
            for (int off = 16; off > 0; off >>= 1)
                ps += __shfl_xor_sync(0xffffffffu, ps, off);
            lrun[r] = lrun[r] * sc + ps;
            mrun[r] = mnew;
            u64 scp = pack2(sc, sc);
            #pragma unroll
            for (int i = 0; i < 8; i++) fmul2(acc[r][i], scp);
            sp[(warp * 4 + r) * BN + nl0] = pack2(p0, p0);
            sp[(warp * 4 + r) * BN + nl1] = pack2(p1, p1);
        }
        __syncwarp();

        // ---- PV ----
        #pragma unroll 2
        for (int n = 0; n < BN; n++) {
            u64 p0 = sp[(warp * 4 + 0) * BN + n];
            u64 p1 = sp[(warp * 4 + 1) * BN + n];
            u64 p2 = sp[(warp * 4 + 2) * BN + n];
            u64 p3 = sp[(warp * 4 + 3) * BN + n];
            #pragma unroll
            for (int k = 0; k < 4; k++) {
                int j = lane + 32 * k;
                ulonglong2 yv = sy[j * BN + (n ^ (j & 63))];
                ffma2(acc[0][2*k], p0, yv.x); ffma2(acc[0][2*k+1], p0, yv.y);
                ffma2(acc[1][2*k], p1, yv.x); ffma2(acc[1][2*k+1], p1, yv.y);
                ffma2(acc[2][2*k], p2, yv.x); ffma2(acc[2][2*k+1], p2, yv.y);
                ffma2(acc[3][2*k], p3, yv.x); ffma2(acc[3][2*k+1], p3, yv.y);
            }
        }
    }

    // ---- write per-(row,split) partials ----
    {
        ulonglong2* gacc2 = (ulonglong2*)g_acc;
        #pragma unroll
        for (int r = 0; r < 4; r++) {
            int row = r0 + warp * 4 + r;
            size_t base = ((size_t)row * NSPLIT + split) * D4;
            #pragma unroll
            for (int k = 0; k < 4; k++)
                gacc2[base + lane + 32 * k] =
                    make_ulonglong2(acc[r][2*k], acc[r][2*k+1]);
            if (lane == 0) {
                g_ml[(row * NSPLIT + split) * 2 + 0] = mrun[r];
                g_ml[(row * NSPLIT + split) * 2 + 1] = lrun[r];
            }
        }
    }

    // ---- last-CTA combine epilogue ----
    __threadfence();
    __syncthreads();
    if (tid == 0) {
        int old = atomicAdd(&g_cnt[rb], 1);
        s_last = (old == NSPLIT - 1) ? 1 : 0;
    }
    __syncthreads();
    if (!s_last) return;
    __threadfence();

    {
        int row = r0 + (tid >> 3);           // 8 threads per row
        int jc  = tid & 7;
        float ms[NSPLIT], ls[NSPLIT];
        float M = -INFINITY;
        #pragma unroll
        for (int s = 0; s < NSPLIT; s++) {
            float2 ml = __ldcg((const float2*)&g_ml[(row * NSPLIT + s) * 2]);
            ms[s] = ml.x; ls[s] = ml.y;
            M = fmaxf(M, ms[s]);
        }
        float w[NSPLIT], L = 0.f;
        #pragma unroll
        for (int s = 0; s < NSPLIT; s++) {
            w[s] = __expf(ms[s] - M);
            L = fmaf(w[s], ls[s], L);
        }
        float a = t[row], b = 1.f - a;
        float c1 = -1.f / b;
        float c2 = (1.f + a / b) / L;

        const float4* gacc4 = (const float4*)g_acc;
        #pragma unroll 4
        for (int q = 0; q < 16; q++) {
            int j = jc + 8 * q;
            float4 ws = make_float4(0.f, 0.f, 0.f, 0.f);
            #pragma unroll
            for (int s = 0; s < NSPLIT; s++) {
                float4 v = __ldcg(&gacc4[((size_t)row * NSPLIT + s) * D4 + j]);
                ws.x = fmaf(w[s], v.x, ws.x); ws.y = fmaf(w[s], v.y, ws.y);
                ws.z = fmaf(w[s], v.z, ws.z); ws.w = fmaf(w[s], v.w, ws.w);
            }
            float4 xv = x4[(size_t)row * D4 + j];
            float4 o;
            o.x = fmaf(c1, xv.x, c2 * ws.x);
            o.y = fmaf(c1, xv.y, c2 * ws.y);
            o.z = fmaf(c1, xv.z, c2 * ws.z);
            o.w = fmaf(c1, xv.w, c2 * ws.w);
            ((float4*)out)[(size_t)row * D4 + j] = o;
        }
    }
    __syncthreads();
    if (tid == 0) g_cnt[rb] = 0;   // reset for next graph replay
}

// ---------------------------------------------------------------------------
extern "C" void kernel_launch(void* const* d_in, const int* in_sizes, int n_in,
                              void* d_out, int out_size)
{
    const float* x = (const float*)d_in[0];   // x_t (1024,512)
    const float* t = (const float*)d_in[1];   // t (1024,)
    const float* y = (const float*)d_in[2];   // dataset (100000,512)
    float* out = (float*)d_out;

    cudaFuncSetAttribute(flash_kernel,
                         cudaFuncAttributeMaxDynamicSharedMemorySize, SMEM_BYTES);
    flash_kernel<<<dim3(NROWBLK, NSPLIT), THREADS, SMEM_BYTES>>>(x, t, y, out);
}

// round 5
// speedup vs baseline: 1.0059x; 1.0059x over previous
#include <cuda_runtime.h>
#include <math.h>

// Problem shapes (fixed)
#define B_SZ 1024
#define N_SZ 100000
#define D_SZ 512
#define D4   128               // float4 per row
#define BM   32                // rows per CTA (8 warps x 4 rows)
#define BN   64                // keys per tile (2 keys per lane)
#define NSPLIT 9
#define SPL  11112             // ceil(N/NSPLIT)
#define THREADS 256
#define NROWBLK (B_SZ/BM)      // 32

#define SMEM_BYTES (BM*D4*16 + D4*BN*16 + BM*BN*8)   // 65536+131072+16384 = 212992

// Scratch
__device__ float g_ml[B_SZ * NSPLIT * 2];
__device__ float g_acc[(size_t)B_SZ * NSPLIT * D_SZ];
__device__ int   g_cnt[NROWBLK];   // zero-initialized; last CTA resets after use

// ---- packed f32x2 helpers (SASS FFMA2 — only reachable via PTX) ----
typedef unsigned long long u64;
__device__ __forceinline__ u64 pack2(float a, float b) {
    u64 r; asm("mov.b64 %0,{%1,%2};" : "=l"(r) : "f"(a), "f"(b)); return r;
}
__device__ __forceinline__ void unpack2(u64 v, float& a, float& b) {
    asm("mov.b64 {%0,%1},%2;" : "=f"(a), "=f"(b) : "l"(v));
}
__device__ __forceinline__ void ffma2(u64& d, u64 a, u64 b) {
    asm("fma.rn.f32x2 %0,%1,%2,%0;" : "+l"(d) : "l"(a), "l"(b));
}
__device__ __forceinline__ void fmul2(u64& d, u64 a) {
    asm("mul.rn.f32x2 %0,%0,%1;" : "+l"(d) : "l"(a));
}

// ---------------------------------------------------------------------------
// One fused kernel: flash pass (QK + online softmax + PV) with on-the-fly
// dataset norms, split-K over keys, and last-CTA-per-row-block combine epilogue.
// logit'[b][n] = (a/b^2) * <x_b,y_n> - (a^2/(2b^2)) * ||y_n||^2   (||x||^2 cancels)
// v = (-1/b) x + (1 + a/b) * softmax-weighted dataset
// ---------------------------------------------------------------------------
__global__ __launch_bounds__(THREADS, 1) void flash_kernel(
    const float* __restrict__ x, const float* __restrict__ t,
    const float* __restrict__ y, float* __restrict__ out)
{
    extern __shared__ char smem_raw[];
    ulonglong2* sx = (ulonglong2*)smem_raw;          // BM*D4 (float4 each)
    ulonglong2* sy = sx + BM * D4;                   // D4*BN, swizzled
    u64*        sp = (u64*)(sy + (size_t)D4 * BN);   // BM*BN packed {p,p}
    __shared__ int s_last;

    const int tid  = threadIdx.x;
    const int lane = tid & 31;
    const int warp = tid >> 5;
    const int rb      = blockIdx.x;
    const int r0      = rb * BM;
    const int split   = blockIdx.y;
    const int n_begin = split * SPL;
    const int n_end   = min(n_begin + SPL, N_SZ);

    // query tile -> smem
    const float4* x4 = (const float4*)x;
    for (int i = tid; i < BM * D4; i += THREADS)
        ((float4*)sx)[i] = x4[(size_t)r0 * D4 + i];

    // per-row coefficients (4 rows per warp)
    float al[4], be[4];
    #pragma unroll
    for (int r = 0; r < 4; r++) {
        float tv = t[r0 + warp * 4 + r];
        float a = tv, b = 1.f - tv;
        al[r] = a / (b * b);
        be[r] = a * a / (2.f * b * b);
    }

    float mrun[4] = {-INFINITY, -INFINITY, -INFINITY, -INFINITY};
    float lrun[4] = {0.f, 0.f, 0.f, 0.f};
    u64 acc[4][8];                       // lane owns d4 = lane+32k -> 2 u64 per k
    #pragma unroll
    for (int r = 0; r < 4; r++)
        #pragma unroll
        for (int i = 0; i < 8; i++) acc[r][i] = 0ull;

    const float4* y4g = (const float4*)y;
    const int nl0 = lane, nl1 = lane + 32;

    for (int n0 = n_begin; n0 < n_end; n0 += BN) {
        __syncthreads();
        // key tile -> smem (swizzled: float4 (n,j) at sy[j*BN + (n ^ (j&63))])
        for (int i = tid; i < BN * D4; i += THREADS) {
            int n = i >> 7, j = i & 127;
            float4 v = make_float4(0.f, 0.f, 0.f, 0.f);
            if (n0 + n < n_end) v = y4g[(size_t)(n0 + n) * D4 + j];
            ((float4*)sy)[j * BN + (n ^ (j & 63))] = v;
        }
        __syncthreads();

        // ---- QK (+ on-the-fly key norms) ----
        u64 s[4][2];
        #pragma unroll
        for (int r = 0; r < 4; r++) { s[r][0] = 0ull; s[r][1] = 0ull; }
        u64 ny0 = 0ull, ny1 = 0ull;

        #pragma unroll 4
        for (int j = 0; j < D4; j++) {
            int c = j & 63;
            ulonglong2 yv0 = sy[j * BN + (nl0 ^ c)];
            ulonglong2 yv1 = sy[j * BN + (nl1 ^ c)];
            ffma2(ny0, yv0.x, yv0.x); ffma2(ny0, yv0.y, yv0.y);
            ffma2(ny1, yv1.x, yv1.x); ffma2(ny1, yv1.y, yv1.y);
            #pragma unroll
            for (int r = 0; r < 4; r++) {
                ulonglong2 xv = sx[(warp * 4 + r) * D4 + j];   // broadcast
                ffma2(s[r][0], xv.x, yv0.x); ffma2(s[r][0], xv.y, yv0.y);
                ffma2(s[r][1], xv.x, yv1.x); ffma2(s[r][1], xv.y, yv1.y);
            }
        }

        bool v0 = (n0 + nl0) < n_end;
        bool v1 = (n0 + nl1) < n_end;
        float t0, t1;
        unpack2(ny0, t0, t1); float dn0 = t0 + t1;
        unpack2(ny1, t0, t1); float dn1 = t0 + t1;

        float lg0[4], lg1[4];
        #pragma unroll
        for (int r = 0; r < 4; r++) {
            float slo, shi, sv;
            unpack2(s[r][0], slo, shi); sv = slo + shi;
            lg0[r] = v0 ? fmaf(al[r], sv, -be[r] * dn0) : -INFINITY;
            unpack2(s[r][1], slo, shi); sv = slo + shi;
            lg1[r] = v1 ? fmaf(al[r], sv, -be[r] * dn1) : -INFINITY;
        }

        // ---- online softmax (4 rows) ----
        #pragma unroll
        for (int r = 0; r < 4; r++) {
            float mt = fmaxf(lg0[r], lg1[r]);
            #pragma unroll
            for (int off = 16; off > 0; off >>= 1)
                mt = fmaxf(mt, __shfl_xor_sync(0xffffffffu, mt, off));
            float mnew = fmaxf(mrun[r], mt);
            float sc = (mrun[r] == -INFINITY) ? 0.f : __expf(mrun[r] - mnew);
            float p0 = __expf(lg0[r] - mnew);
            float p1 = __expf(lg1[r] - mnew);
            float ps = p0 + p1;
            #pragma unroll
            for (int off = 16; off > 0; off >>= 1)
                ps += __shfl_xor_sync(0xffffffffu, ps, off);
            lrun[r] = lrun[r] * sc + ps;
            mrun[r] = mnew;
            u64 scp = pack2(sc, sc);
            #pragma unroll
            for (int i = 0; i < 8; i++) fmul2(acc[r][i], scp);
            sp[(warp * 4 + r) * BN + nl0] = pack2(p0, p0);
            sp[(warp * 4 + r) * BN + nl1] = pack2(p1, p1);
        }
        __syncwarp();

        // ---- PV ----
        #pragma unroll 2
        for (int n = 0; n < BN; n++) {
            u64 p0 = sp[(warp * 4 + 0) * BN + n];
            u64 p1 = sp[(warp * 4 + 1) * BN + n];
            u64 p2 = sp[(warp * 4 + 2) * BN + n];
            u64 p3 = sp[(warp * 4 + 3) * BN + n];
            #pragma unroll
            for (int k = 0; k < 4; k++) {
                int j = lane + 32 * k;
                ulonglong2 yv = sy[j * BN + (n ^ (j & 63))];
                ffma2(acc[0][2*k], p0, yv.x); ffma2(acc[0][2*k+1], p0, yv.y);
                ffma2(acc[1][2*k], p1, yv.x); ffma2(acc[1][2*k+1], p1, yv.y);
                ffma2(acc[2][2*k], p2, yv.x); ffma2(acc[2][2*k+1], p2, yv.y);
                ffma2(acc[3][2*k], p3, yv.x); ffma2(acc[3][2*k+1], p3, yv.y);
            }
        }
    }

    // ---- write per-(row,split) partials ----
    {
        ulonglong2* gacc2 = (ulonglong2*)g_acc;
        #pragma unroll
        for (int r = 0; r < 4; r++) {
            int row = r0 + warp * 4 + r;
            size_t base = ((size_t)row * NSPLIT + split) * D4;
            #pragma unroll
            for (int k = 0; k < 4; k++)
                gacc2[base + lane + 32 * k] =
                    make_ulonglong2(acc[r][2*k], acc[r][2*k+1]);
            if (lane == 0) {
                g_ml[(row * NSPLIT + split) * 2 + 0] = mrun[r];
                g_ml[(row * NSPLIT + split) * 2 + 1] = lrun[r];
            }
        }
    }

    // ---- last-CTA combine epilogue ----
    __threadfence();
    __syncthreads();
    if (tid == 0) {
        int old = atomicAdd(&g_cnt[rb], 1);
        s_last = (old == NSPLIT - 1) ? 1 : 0;
    }
    __syncthreads();
    if (!s_last) return;
    __threadfence();

    {
        int row = r0 + (tid >> 3);           // 8 threads per row
        int jc  = tid & 7;
        float ms[NSPLIT], ls[NSPLIT];
        float M = -INFINITY;
        #pragma unroll
        for (int s = 0; s < NSPLIT; s++) {
            float2 ml = __ldcg((const float2*)&g_ml[(row * NSPLIT + s) * 2]);
            ms[s] = ml.x; ls[s] = ml.y;
            M = fmaxf(M, ms[s]);
        }
        float w[NSPLIT], L = 0.f;
        #pragma unroll
        for (int s = 0; s < NSPLIT; s++) {
            w[s] = __expf(ms[s] - M);
            L = fmaf(w[s], ls[s], L);
        }
        float a = t[row], b = 1.f - a;
        float c1 = -1.f / b;
        float c2 = (1.f + a / b) / L;

        const float4* gacc4 = (const float4*)g_acc;
        #pragma unroll 4
        for (int q = 0; q < 16; q++) {
            int j = jc + 8 * q;
            float4 ws = make_float4(0.f, 0.f, 0.f, 0.f);
            #pragma unroll
            for (int s = 0; s < NSPLIT; s++) {
                float4 v = __ldcg(&gacc4[((size_t)row * NSPLIT + s) * D4 + j]);
                ws.x = fmaf(w[s], v.x, ws.x); ws.y = fmaf(w[s], v.y, ws.y);
                ws.z = fmaf(w[s], v.z, ws.z); ws.w = fmaf(w[s], v.w, ws.w);
            }
            float4 xv = x4[(size_t)row * D4 + j];
            float4 o;
            o.x = fmaf(c1, xv.x, c2 * ws.x);
            o.y = fmaf(c1, xv.y, c2 * ws.y);
            o.z = fmaf(c1, xv.z, c2 * ws.z);
            o.w = fmaf(c1, xv.w, c2 * ws.w);
            ((float4*)out)[(size_t)row * D4 + j] = o;
        }
    }
    __syncthreads();
    if (tid == 0) g_cnt[rb] = 0;   // reset for next graph replay
}

// ---------------------------------------------------------------------------
extern "C" void kernel_launch(void* const* d_in, const int* in_sizes, int n_in,
                              void* d_out, int out_size)
{
    const float* x = (const float*)d_in[0];   // x_t (1024,512)
    const float* t = (const float*)d_in[1];   // t (1024,)
    const float* y = (const float*)d_in[2];   // dataset (100000,512)
    float* out = (float*)d_out;

    cudaFuncSetAttribute(flash_kernel,
                         cudaFuncAttributeMaxDynamicSharedMemorySize, SMEM_BYTES);
    flash_kernel<<<dim3(NROWBLK, NSPLIT), THREADS, SMEM_BYTES>>>(x, t, y, out);
}

// round 6
// speedup vs baseline: 1.1350x; 1.1283x over previous
#include <cuda_runtime.h>
#include <math.h>

// Problem shapes (fixed)
#define B_SZ 1024
#define N_SZ 100000
#define D_SZ 512
#define D4   128               // float4 per row
#define RPW  6                 // rows per warp
#define BM   48                // 8 warps * 6 rows
#define BN   64                // keys per tile (2 per lane)
#define NSPLIT 13
#define SPL  7693              // ceil(N/NSPLIT)
#define THREADS 256
#define NRB  22                // ceil(B/BM)

#define SMEM_BYTES ((BM*D4 + D4*BN)*16)   // 96KB + 128KB = 229376

// Scratch
__device__ float g_ml[B_SZ * NSPLIT * 2];
__device__ float g_acc[(size_t)B_SZ * NSPLIT * D_SZ];
__device__ int   g_cnt[NRB];   // zero-init; last CTA resets after use

typedef unsigned long long u64;
__device__ __forceinline__ u64 pack2(float a, float b) {
    u64 r; asm("mov.b64 %0,{%1,%2};" : "=l"(r) : "f"(a), "f"(b)); return r;
}
__device__ __forceinline__ void unpack2(u64 v, float& a, float& b) {
    asm("mov.b64 {%0,%1},%2;" : "=f"(a), "=f"(b) : "l"(v));
}
__device__ __forceinline__ void ffma2(u64& d, u64 a, u64 b) {
    asm("fma.rn.f32x2 %0,%1,%2,%0;" : "+l"(d) : "l"(a), "l"(b));
}
__device__ __forceinline__ void fmul2(u64& d, u64 a) {
    asm("mul.rn.f32x2 %0,%0,%1;" : "+l"(d) : "l"(a));
}
__device__ __forceinline__ void cp16(unsigned dst, const void* src) {
    asm volatile("cp.async.cg.shared.global [%0], [%1], 16;" :: "r"(dst), "l"(src));
}

// ---------------------------------------------------------------------------
// Fused flash kernel: QK (+on-the-fly key norms) -> online softmax -> PV,
// split over keys, last-CTA-per-row-block combine epilogue.
// logit'[b][n] = (a/b^2)*<x_b,y_n> - (a^2/(2b^2))*||y_n||^2
// v = (-1/b) x + (1 + a/b) * softmax-weighted dataset
// ---------------------------------------------------------------------------
__global__ __launch_bounds__(THREADS, 1) void flash_kernel(
    const float* __restrict__ x, const float* __restrict__ t,
    const float* __restrict__ y, float* __restrict__ out)
{
    extern __shared__ char smem_raw[];
    ulonglong2* sx = (ulonglong2*)smem_raw;        // BM*D4 float4
    ulonglong2* sy = sx + BM * D4;                 // D4*BN float4, swizzled
    __shared__ int s_last;

    const int tid  = threadIdx.x;
    const int lane = tid & 31;
    const int warp = tid >> 5;
    const int rb      = blockIdx.x;
    const int r0      = rb * BM;
    const int split   = blockIdx.y;
    const int n_begin = split * SPL;
    const int n_end   = min(n_begin + SPL, N_SZ);

    const unsigned sx_u = (unsigned)__cvta_generic_to_shared(sx);
    const unsigned sy_u = (unsigned)__cvta_generic_to_shared(sy);

    // query tile -> smem via cp.async (row-clamped for the ragged last block)
    const float4* x4 = (const float4*)x;
    for (int i = tid; i < BM * D4; i += THREADS) {
        int rc = min(r0 + (i >> 7), B_SZ - 1);
        cp16(sx_u + i * 16, &x4[(size_t)rc * D4 + (i & 127)]);
    }

    // per-row coefficients
    float al[RPW], be[RPW];
    #pragma unroll
    for (int r = 0; r < RPW; r++) {
        int row = min(r0 + warp * RPW + r, B_SZ - 1);
        float tv = t[row];
        float a = tv, b = 1.f - tv;
        al[r] = a / (b * b);
        be[r] = a * a / (2.f * b * b);
    }

    float mrun[RPW], lrun[RPW];
    u64 acc[RPW][8];
    #pragma unroll
    for (int r = 0; r < RPW; r++) {
        mrun[r] = -INFINITY; lrun[r] = 0.f;
        #pragma unroll
        for (int i = 0; i < 8; i++) acc[r][i] = 0ull;
    }

    const float4* y4g = (const float4*)y;
    const int nl0 = lane, nl1 = lane + 32;

    for (int n0 = n_begin; n0 < n_end; n0 += BN) {
        __syncthreads();   // previous tile's readers done with sy
        // key tile -> smem, swizzled: float4 (n,j) at sy[j*BN + (n ^ (j&63))].
        // OOB keys clamp the gmem source (valid memory); results masked later.
        for (int i = tid; i < BN * D4; i += THREADS) {
            int n = i >> 7, j = i & 127;
            int nc = min(n0 + n, N_SZ - 1);
            cp16(sy_u + (j * BN + (n ^ (j & 63))) * 16,
                 &y4g[(size_t)nc * D4 + j]);
        }
        asm volatile("cp.async.commit_group;");
        asm volatile("cp.async.wait_group 0;");
        __syncthreads();

        // ---- QK (+ key norms) ----
        u64 s[RPW][2];
        #pragma unroll
        for (int r = 0; r < RPW; r++) { s[r][0] = 0ull; s[r][1] = 0ull; }
        u64 ny0 = 0ull, ny1 = 0ull;

        #pragma unroll 2
        for (int j = 0; j < D4; j++) {
            int c = j & 63;
            ulonglong2 yv0 = sy[j * BN + (nl0 ^ c)];
            ulonglong2 yv1 = sy[j * BN + (nl1 ^ c)];
            ffma2(ny0, yv0.x, yv0.x); ffma2(ny0, yv0.y, yv0.y);
            ffma2(ny1, yv1.x, yv1.x); ffma2(ny1, yv1.y, yv1.y);
            #pragma unroll
            for (int r = 0; r < RPW; r++) {
                ulonglong2 xv = sx[(warp * RPW + r) * D4 + j];  // broadcast
                ffma2(s[r][0], xv.x, yv0.x); ffma2(s[r][0], xv.y, yv0.y);
                ffma2(s[r][1], xv.x, yv1.x); ffma2(s[r][1], xv.y, yv1.y);
            }
        }

        bool v0 = (n0 + nl0) < n_end;
        bool v1 = (n0 + nl1) < n_end;
        float t0, t1;
        unpack2(ny0, t0, t1); float dn0 = t0 + t1;
        unpack2(ny1, t0, t1); float dn1 = t0 + t1;

        // ---- online softmax (RPW rows); p kept in registers ----
        float p0[RPW], p1[RPW];
        #pragma unroll
        for (int r = 0; r < RPW; r++) {
            float slo, shi, sv;
            unpack2(s[r][0], slo, shi); sv = slo + shi;
            float lg0 = v0 ? fmaf(al[r], sv, -be[r] * dn0) : -INFINITY;
            unpack2(s[r][1], slo, shi); sv = slo + shi;
            float lg1 = v1 ? fmaf(al[r], sv, -be[r] * dn1) : -INFINITY;

            float mt = fmaxf(lg0, lg1);
            #pragma unroll
            for (int off = 16; off > 0; off >>= 1)
                mt = fmaxf(mt, __shfl_xor_sync(0xffffffffu, mt, off));
            float mnew = fmaxf(mrun[r], mt);
            float sc = (mrun[r] == -INFINITY) ? 0.f : __expf(mrun[r] - mnew);
            p0[r] = __expf(lg0 - mnew);
            p1[r] = __expf(lg1 - mnew);
            float ps = p0[r] + p1[r];
            #pragma unroll
            for (int off = 16; off > 0; off >>= 1)
                ps += __shfl_xor_sync(0xffffffffu, ps, off);
            lrun[r] = lrun[r] * sc + ps;
            mrun[r] = mnew;
            u64 scp = pack2(sc, sc);
            #pragma unroll
            for (int i = 0; i < 8; i++) fmul2(acc[r][i], scp);
        }

        // ---- PV: p broadcast via shfl (lane nn owns key n0+nn / n0+32+nn) ----
        #pragma unroll 2
        for (int nn = 0; nn < 32; nn++) {
            u64 pp[RPW];
            #pragma unroll
            for (int r = 0; r < RPW; r++) {
                float pv = __shfl_sync(0xffffffffu, p0[r], nn);
                pp[r] = pack2(pv, pv);
            }
            #pragma unroll
            for (int k = 0; k < 4; k++) {
                int j = lane + 32 * k;
                ulonglong2 yv = sy[j * BN + (nn ^ (j & 63))];
                #pragma unroll
                for (int r = 0; r < RPW; r++) {
                    ffma2(acc[r][2*k],   pp[r], yv.x);
                    ffma2(acc[r][2*k+1], pp[r], yv.y);
                }
            }
        }
        #pragma unroll 2
        for (int nn = 0; nn < 32; nn++) {
            int n = nn + 32;
            u64 pp[RPW];
            #pragma unroll
            for (int r = 0; r < RPW; r++) {
                float pv = __shfl_sync(0xffffffffu, p1[r], nn);
                pp[r] = pack2(pv, pv);
            }
            #pragma unroll
            for (int k = 0; k < 4; k++) {
                int j = lane + 32 * k;
                ulonglong2 yv = sy[j * BN + (n ^ (j & 63))];
                #pragma unroll
                for (int r = 0; r < RPW; r++) {
                    ffma2(acc[r][2*k],   pp[r], yv.x);
                    ffma2(acc[r][2*k+1], pp[r], yv.y);
                }
            }
        }
    }

    // ---- write per-(row,split) partials (skip rows >= B) ----
    {
        ulonglong2* gacc2 = (ulonglong2*)g_acc;
        #pragma unroll
        for (int r = 0; r < RPW; r++) {
            int row = r0 + warp * RPW + r;
            if (row < B_SZ) {
                size_t base = ((size_t)row * NSPLIT + split) * D4;
                #pragma unroll
                for (int k = 0; k < 4; k++)
                    gacc2[base + lane + 32 * k] =
                        make_ulonglong2(acc[r][2*k], acc[r][2*k+1]);
                if (lane == 0) {
                    g_ml[(row * NSPLIT + split) * 2 + 0] = mrun[r];
                    g_ml[(row * NSPLIT + split) * 2 + 1] = lrun[r];
                }
            }
        }
    }

    // ---- last-CTA combine epilogue ----
    __threadfence();
    __syncthreads();
    if (tid == 0) {
        int old = atomicAdd(&g_cnt[rb], 1);
        s_last = (old == NSPLIT - 1) ? 1 : 0;
    }
    __syncthreads();
    if (!s_last) return;
    __threadfence();

    // 256 threads: 8 threads per row, 32 rows per pass, 2 passes for BM=48
    #pragma unroll
    for (int pass = 0; pass < 2; pass++) {
        int rl = pass * 32 + (tid >> 3);
        int row = r0 + rl;
        if (rl < BM && row < B_SZ) {
            int jc = tid & 7;
            float ms[NSPLIT], ls[NSPLIT];
            float M = -INFINITY;
            #pragma unroll
            for (int s = 0; s < NSPLIT; s++) {
                float2 ml = __ldcg((const float2*)&g_ml[(row * NSPLIT + s) * 2]);
                ms[s] = ml.x; ls[s] = ml.y;
                M = fmaxf(M, ms[s]);
            }
            float w[NSPLIT], L = 0.f;
            #pragma unroll
            for (int s = 0; s < NSPLIT; s++) {
                w[s] = __expf(ms[s] - M);
                L = fmaf(w[s], ls[s], L);
            }
            float a = t[row], b = 1.f - a;
            float c1 = -1.f / b;
            float c2 = (1.f + a / b) / L;

            const float4* gacc4 = (const float4*)g_acc;
            #pragma unroll 4
            for (int q = 0; q < 16; q++) {
                int j = jc + 8 * q;
                float4 ws = make_float4(0.f, 0.f, 0.f, 0.f);
                #pragma unroll
                for (int s = 0; s < NSPLIT; s++) {
                    float4 v = __ldcg(&gacc4[((size_t)row * NSPLIT + s) * D4 + j]);
                    ws.x = fmaf(w[s], v.x, ws.x); ws.y = fmaf(w[s], v.y, ws.y);
                    ws.z = fmaf(w[s], v.z, ws.z); ws.w = fmaf(w[s], v.w, ws.w);
                }
                float4 xv = x4[(size_t)row * D4 + j];
                float4 o;
                o.x = fmaf(c1, xv.x, c2 * ws.x);
                o.y = fmaf(c1, xv.y, c2 * ws.y);
                o.z = fmaf(c1, xv.z, c2 * ws.z);
                o.w = fmaf(c1, xv.w, c2 * ws.w);
                ((float4*)out)[(size_t)row * D4 + j] = o;
            }
        }
    }
    __syncthreads();
    if (tid == 0) g_cnt[rb] = 0;   // reset for next graph replay
}

// ---------------------------------------------------------------------------
extern "C" void kernel_launch(void* const* d_in, const int* in_sizes, int n_in,
                              void* d_out, int out_size)
{
    const float* x = (const float*)d_in[0];   // x_t (1024,512)
    const float* t = (const float*)d_in[1];   // t (1024,)
    const float* y = (const float*)d_in[2];   // dataset (100000,512)
    float* out = (float*)d_out;

    cudaFuncSetAttribute(flash_kernel,
                         cudaFuncAttributeMaxDynamicSharedMemorySize, SMEM_BYTES);
    flash_kernel<<<dim3(NRB, NSPLIT), THREADS, SMEM_BYTES>>>(x, t, y, out);
}